// round 6
// baseline (speedup 1.0000x reference)
#include <cuda_runtime.h>
#include <cstdint>

#define BATCH 512
#define TLEN  8192
#define DTC   1e-3f
#define CHUNK 2048             // steps per block
#define CPR   (TLEN / CHUNK)   // 4 chunks per row
#define NBLK  (BATCH * CPR)    // 2048 blocks
#define NWARP 8
#define NTHR  (NWARP * 32)     // 256
#define LS    (CHUNK / NTHR)   // 8 steps per lane

// padded smem index: row = 8 steps + 1 pad slot
__device__ __forceinline__ int sidx(int s) { return (s >> 3) * 9 + (s & 7); }
#define ROWS      (CHUNK / 8)            // 256
#define SQ_ELEMS  (ROWS * 9)             // 2304 float4
#define SQ_BYTES  (SQ_ELEMS * 16)        // 36864
#define SD_BYTES  (SQ_ELEMS * 8)         // 18432
#define SMEM_BYTES (SQ_BYTES + SD_BYTES) // 55296 (dynamic)

// decoupled-lookback state
__device__ int   g_status[NBLK];      // 0=none, 1=aggregate, 2=inclusive
__device__ float g_agg[NBLK][6];      // chunk affine aggregate
__device__ float g_inc[NBLK][2];      // state at END of chunk

__device__ __forceinline__ void cp16(uint32_t dst, const void* src) {
    asm volatile("cp.async.cg.shared.global [%0], [%1], 16;" :: "r"(dst), "l"(src));
}
__device__ __forceinline__ void cp8(uint32_t dst, const void* src) {
    asm volatile("cp.async.ca.shared.global [%0], [%1], 8;" :: "r"(dst), "l"(src));
}
__device__ __forceinline__ void cp_commit() { asm volatile("cp.async.commit_group;"); }
__device__ __forceinline__ void cp_wait0()  { asm volatile("cp.async.wait_group 0;"); }

// self = self ∘ prev (prev applied first)
__device__ __forceinline__ void compose(float& M00, float& M01, float& M10, float& M11,
                                        float& v0, float& v1,
                                        float pM00, float pM01, float pM10, float pM11,
                                        float pv0, float pv1) {
    float n00 = M00 * pM00 + M01 * pM10;
    float n01 = M00 * pM01 + M01 * pM11;
    float n10 = M10 * pM00 + M11 * pM10;
    float n11 = M10 * pM01 + M11 * pM11;
    float nv0 = M00 * pv0 + M01 * pv1 + v0;
    float nv1 = M10 * pv0 + M11 * pv1 + v1;
    M00 = n00; M01 = n01; M10 = n10; M11 = n11; v0 = nv0; v1 = nv1;
}

__device__ __forceinline__ void warp_inclusive_scan(float& M00, float& M01, float& M10, float& M11,
                                                    float& v0, float& v1, int lane) {
    #pragma unroll
    for (int d = 1; d < 32; d <<= 1) {
        float pM00 = __shfl_up_sync(0xffffffffu, M00, d);
        float pM01 = __shfl_up_sync(0xffffffffu, M01, d);
        float pM10 = __shfl_up_sync(0xffffffffu, M10, d);
        float pM11 = __shfl_up_sync(0xffffffffu, M11, d);
        float pv0  = __shfl_up_sync(0xffffffffu, v0,  d);
        float pv1  = __shfl_up_sync(0xffffffffu, v1,  d);
        if (lane >= d) compose(M00, M01, M10, M11, v0, v1, pM00, pM01, pM10, pM11, pv0, pv1);
    }
}

__device__ __forceinline__ void step_transform(float4 q, float2 d,
                                               float a00, float a01, float a10, float a11,
                                               float c00, float c01, float c10, float c11,
                                               float& T00, float& T01, float& T10, float& T11,
                                               float& b0, float& b1) {
    T00 = 1.0f + DTC * (a00 - (q.x * c00 + q.y * c10));
    T01 =        DTC * (a01 - (q.x * c01 + q.y * c11));
    T10 =        DTC * (a10 - (q.z * c00 + q.w * c10));
    T11 = 1.0f + DTC * (a11 - (q.z * c01 + q.w * c11));
    b0  = q.x * d.x + q.y * d.y;
    b1  = q.z * d.x + q.w * d.y;
}

__global__ void kReset() {
    int i = blockIdx.x * blockDim.x + threadIdx.x;
    if (i < NBLK) g_status[i] = 0;
}

// ---------------- Single-pass decoupled-lookback kernel ----------------
__global__ __launch_bounds__(NTHR)
void kScan(const float4* __restrict__ xic, const float2* __restrict__ dyv,
           const float* __restrict__ Ac, const float* __restrict__ Cm,
           float2* __restrict__ out) {
    extern __shared__ char smem[];
    float4* sq = (float4*)smem;                    // q tile, later holds T (transform)
    float2* sd = (float2*)(smem + SQ_BYTES);       // d tile, later holds b (offset)

    __shared__ float wc[NWARP][6];     // warp composites
    __shared__ float pc[NWARP][6];     // exclusive prefix composites per warp
    __shared__ float carry[2];         // x_start of this chunk

    const int tid  = threadIdx.x;
    const int lane = tid & 31;
    const int w    = tid >> 5;
    const int bid  = blockIdx.x;
    const int row  = bid >> 2;         // CPR == 4
    const int chunk = bid & 3;

    const float c00 = __ldg(Cm + 0), c01 = __ldg(Cm + 1), c10 = __ldg(Cm + 2), c11 = __ldg(Cm + 3);
    const float a00 = __ldg(Ac + 0), a01 = __ldg(Ac + 1), a10 = __ldg(Ac + 2), a11 = __ldg(Ac + 3);

    const size_t base = (size_t)row * TLEN + (size_t)chunk * CHUNK;
    const uint32_t smem_u32 = (uint32_t)__cvta_generic_to_shared(smem);

    // --- stage tile (coalesced cp.async) ---
    {
        const float4* xp = xic + base;
        const float2* dp = dyv + base;
        #pragma unroll
        for (int j = 0; j < CHUNK / NTHR; j++) {
            int s = j * NTHR + tid;
            int si = sidx(s);
            cp16(smem_u32 + si * 16, xp + s);
            cp8(smem_u32 + SQ_BYTES + si * 8, dp + s);
        }
        cp_commit();
        cp_wait0();
    }
    __syncthreads();   // sync1

    // --- per-lane composite of 8 steps; cache T,b back into the consumed slots ---
    const int s0 = w * (32 * LS) + lane * LS;
    float M00 = 1.f, M01 = 0.f, M10 = 0.f, M11 = 1.f, v0 = 0.f, v1 = 0.f;
    #pragma unroll
    for (int k = 0; k < LS; k++) {
        int si = sidx(s0 + k);
        float4 q = sq[si];
        float2 d = sd[si];
        float T00, T01, T10, T11, b0, b1;
        step_transform(q, d, a00, a01, a10, a11, c00, c01, c10, c11, T00, T01, T10, T11, b0, b1);
        sq[si] = make_float4(T00, T01, T10, T11);   // lane-private slot, no race
        sd[si] = make_float2(b0, b1);
        float n00 = T00 * M00 + T01 * M10;
        float n01 = T00 * M01 + T01 * M11;
        float n10 = T10 * M00 + T11 * M10;
        float n11 = T10 * M01 + T11 * M11;
        float nv0 = T00 * v0 + T01 * v1 + b0;
        float nv1 = T10 * v0 + T11 * v1 + b1;
        M00 = n00; M01 = n01; M10 = n10; M11 = n11; v0 = nv0; v1 = nv1;
    }

    warp_inclusive_scan(M00, M01, M10, M11, v0, v1, lane);

    if (lane == 31) {
        wc[w][0] = M00; wc[w][1] = M01; wc[w][2] = M10;
        wc[w][3] = M11; wc[w][4] = v0;  wc[w][5] = v1;
    }
    __syncthreads();   // sync2

    // --- thread 0: aggregate, publish, lookback, publish inclusive ---
    if (tid == 0) {
        // chain warp composites; pc[i] = composite of warps < i
        float P00 = 1.f, P01 = 0.f, P10 = 0.f, P11 = 1.f, Pv0 = 0.f, Pv1 = 0.f;
        #pragma unroll
        for (int i = 0; i < NWARP; i++) {
            pc[i][0] = P00; pc[i][1] = P01; pc[i][2] = P10;
            pc[i][3] = P11; pc[i][4] = Pv0; pc[i][5] = Pv1;
            float W00 = wc[i][0], W01 = wc[i][1], W10 = wc[i][2];
            float W11 = wc[i][3], Wv0 = wc[i][4], Wv1 = wc[i][5];
            compose(W00, W01, W10, W11, Wv0, Wv1, P00, P01, P10, P11, Pv0, Pv1);
            P00 = W00; P01 = W01; P10 = W10; P11 = W11; Pv0 = Wv0; Pv1 = Wv1;
        }

        volatile float* agg = g_agg[bid];
        volatile float* inc = g_inc[bid];

        float xs0, xs1;
        if (chunk == 0) {
            xs0 = 1.f; xs1 = 0.f;
        } else {
            // publish aggregate first
            agg[0] = P00; agg[1] = P01; agg[2] = P10;
            agg[3] = P11; agg[4] = Pv0; agg[5] = Pv1;
            __threadfence();
            atomicExch(&g_status[bid], 1);

            // lookback (depth <= 3); R accumulates suffix composite
            float R00 = 1.f, R01 = 0.f, R10 = 0.f, R11 = 1.f, Rv0 = 0.f, Rv1 = 0.f;
            int i = bid - 1;
            for (;;) {
                int s;
                while ((s = atomicAdd(&g_status[i], 0)) == 0) __nanosleep(40);
                __threadfence();
                if (s == 2) {
                    volatile float* pi = g_inc[i];
                    float e0 = pi[0], e1 = pi[1];
                    xs0 = R00 * e0 + R01 * e1 + Rv0;
                    xs1 = R10 * e0 + R11 * e1 + Rv1;
                    break;
                } else {
                    volatile float* pa = g_agg[i];
                    float A0 = pa[0], A1 = pa[1], A2 = pa[2], A3 = pa[3], A4 = pa[4], A5 = pa[5];
                    compose(R00, R01, R10, R11, Rv0, Rv1, A0, A1, A2, A3, A4, A5);
                    i--;
                }
            }
        }

        // publish inclusive (state at end of this chunk)
        inc[0] = P00 * xs0 + P01 * xs1 + Pv0;
        inc[1] = P10 * xs0 + P11 * xs1 + Pv1;
        __threadfence();
        atomicExch(&g_status[bid], 2);

        carry[0] = xs0; carry[1] = xs1;
    }
    __syncthreads();   // sync3

    // --- per-warp start state, exclusive lane prefix ---
    float xs0 = carry[0], xs1 = carry[1];
    float xw0 = pc[w][0] * xs0 + pc[w][1] * xs1 + pc[w][4];
    float xw1 = pc[w][2] * xs0 + pc[w][3] * xs1 + pc[w][5];

    float pM00 = __shfl_up_sync(0xffffffffu, M00, 1);
    float pM01 = __shfl_up_sync(0xffffffffu, M01, 1);
    float pM10 = __shfl_up_sync(0xffffffffu, M10, 1);
    float pM11 = __shfl_up_sync(0xffffffffu, M11, 1);
    float pv0  = __shfl_up_sync(0xffffffffu, v0,  1);
    float pv1  = __shfl_up_sync(0xffffffffu, v1,  1);
    if (lane == 0) { pM00 = 1.f; pM01 = 0.f; pM10 = 0.f; pM11 = 1.f; pv0 = 0.f; pv1 = 0.f; }

    float x0 = pM00 * xw0 + pM01 * xw1 + pv0;
    float x1 = pM10 * xw0 + pM11 * xw1 + pv1;

    // --- replay from cached transforms, write 4 coalesced float4 per lane ---
    float4* op4 = (float4*)(out + base + s0);   // 8 float2 = 4 float4, 64B contiguous
    #pragma unroll
    for (int k = 0; k < LS; k += 2) {
        int si0 = sidx(s0 + k);
        int si1 = sidx(s0 + k + 1);
        float4 T0 = sq[si0]; float2 b0 = sd[si0];
        float4 o;
        o.x = DTC * (c00 * x0 + c01 * x1);
        o.y = DTC * (c10 * x0 + c11 * x1);
        {
            float nx0 = T0.x * x0 + T0.y * x1 + b0.x;
            float nx1 = T0.z * x0 + T0.w * x1 + b0.y;
            x0 = nx0; x1 = nx1;
        }
        o.z = DTC * (c00 * x0 + c01 * x1);
        o.w = DTC * (c10 * x0 + c11 * x1);
        float4 T1 = sq[si1]; float2 b1 = sd[si1];
        {
            float nx0 = T1.x * x0 + T1.y * x1 + b1.x;
            float nx1 = T1.z * x0 + T1.w * x1 + b1.y;
            x0 = nx0; x1 = nx1;
        }
        op4[k >> 1] = o;
    }
}

extern "C" void kernel_launch(void* const* d_in, const int* in_sizes, int n_in,
                              void* d_out, int out_size) {
    const float4* xic = (const float4*)d_in[0];   // [B,T,2,2] f32
    const float2* dyv = (const float2*)d_in[1];   // [B,T,2]   f32
    const float*  Ac  = (const float*)d_in[2];    // [2,2]
    const float*  Cm  = (const float*)d_in[3];    // [2,2]
    float2* out = (float2*)d_out;                 // [B,T,2]

    cudaFuncSetAttribute(kScan, cudaFuncAttributeMaxDynamicSharedMemorySize, SMEM_BYTES);

    kReset<<<(NBLK + 255) / 256, 256>>>();
    kScan<<<NBLK, NTHR, SMEM_BYTES>>>(xic, dyv, Ac, Cm, out);
}